// round 16
// baseline (speedup 1.0000x reference)
#include <cuda_runtime.h>
#include <cuda_fp16.h>
#include <cstring>

#define DD 64
#define NMAX 100000
#define EMAX 1200000

// Portable bit-casts
__device__ __forceinline__ unsigned h2_to_u32(__half2 h) { unsigned u; memcpy(&u, &h, 4); return u; }
__device__ __forceinline__ __half2 u32_to_h2(unsigned u) { __half2 h; memcpy(&h, &u, 4); return h; }

// Scratch (allocation-free rule: __device__ globals). 16B-aligned.
__device__ __align__(16) float  g_deg[NMAX];
__device__ __align__(16) float  g_dis[NMAX];
__device__ __align__(16) int    g_cnt[NMAX];
__device__ __align__(16) int    g_row[NMAX + 1];
__device__ __align__(16) int    g_cur[NMAX];
__device__ __align__(16) float2 g_pair[EMAX];       // (src as int bits, weight), bucketed by dst
__device__ __align__(16) __half g_hs [NMAX * DD];   // fp16: dis*(X@W1)
__device__ __align__(16) __half g_hs2[NMAX * DD];   // fp16: dis*(x1@W2)
__device__ __align__(16) float  g_x1 [NMAX * DD];   // layer-1 output (fp32)

// ---------------------------------------------------------------------------
// init: cnt = 0, deg = 1 (self-loop weight)
__global__ void init_kernel(int n) {
    int i = blockIdx.x * blockDim.x + threadIdx.x;
    if (i < n) { g_cnt[i] = 0; g_deg[i] = 1.0f; }
}

// count in-degree + weighted degree.  edge_index is INT32: src = ei[e], dst = ei[E+e].
__global__ void count_kernel(const int* __restrict__ ei,
                             const float* __restrict__ ew, int E) {
    int e = blockIdx.x * blockDim.x + threadIdx.x;
    if (e < E) {
        int d = ei[E + e];
        atomicAdd(&g_cnt[d], 1);
        atomicAdd(&g_deg[d], ew[e]);
    }
}

// single-block exclusive scan of g_cnt -> g_row, g_cur;
// SINGLE DELTA vs R14: dis = rsqrt(deg) fused into the second sweep.
__global__ __launch_bounds__(1024) void scan_dis_kernel(int n) {
    __shared__ int ssum[1024];
    int t = threadIdx.x;
    int chunk = (n + 1023) >> 10;
    int beg = t * chunk;
    int end = min(n, beg + chunk);
    int s = 0;
    for (int i = beg; i < end; i++) s += g_cnt[i];
    ssum[t] = s;
    __syncthreads();
    if (t == 0) {
        int acc = 0;
        for (int i = 0; i < 1024; i++) { int v = ssum[i]; ssum[i] = acc; acc += v; }
        g_row[n] = acc;
    }
    __syncthreads();
    int acc = ssum[t];
    for (int i = beg; i < end; i++) {
        int c = g_cnt[i];
        g_row[i] = acc;
        g_cur[i] = acc;
        acc += c;
        g_dis[i] = rsqrtf(g_deg[i]);   // deg >= 1 (self-loop)
    }
}

// bucket edges by dst: g_pair[slot] = (src, w)
__global__ void fill_kernel(const int* __restrict__ ei,
                            const float* __restrict__ ew, int E) {
    int e = blockIdx.x * blockDim.x + threadIdx.x;
    if (e < E) {
        int s = ei[e];
        int d = ei[E + e];
        int p = atomicAdd(&g_cur[d], 1);
        g_pair[p] = make_float2(__int_as_float(s), ew[e]);
    }
}

// ---------------------------------------------------------------------------
// Per-thread gather core (R10/R14-proven loop).  16 lanes per node, lane q
// owns 4 fp16 columns (8B).  Returns relu(dis*acc + b) for (d, q).
__device__ __forceinline__ float4 gather_node(const __half* __restrict__ hsrc,
                                              int d, int q, const float* __restrict__ b) {
    const uint2* __restrict__ hs2 = (const uint2*)hsrc;
    size_t oi = (size_t)d * 16 + q;

    uint2 self = hs2[oi];
    float2 s01 = __half22float2(u32_to_h2(self.x));
    float2 s23 = __half22float2(u32_to_h2(self.y));
    float4 acc = make_float4(s01.x, s01.y, s23.x, s23.y);

    int beg = g_row[d];
    int end = g_row[d + 1];

    int i = beg;
    for (; i + 2 <= end; i += 2) {
        float2 p0 = g_pair[i];
        float2 p1 = g_pair[i + 1];
        uint2 r0 = hs2[(size_t)__float_as_int(p0.x) * 16 + q];
        uint2 r1 = hs2[(size_t)__float_as_int(p1.x) * 16 + q];
        float2 a01 = __half22float2(u32_to_h2(r0.x));
        float2 a23 = __half22float2(u32_to_h2(r0.y));
        float2 b01 = __half22float2(u32_to_h2(r1.x));
        float2 b23 = __half22float2(u32_to_h2(r1.y));
        acc.x = fmaf(p0.y, a01.x, acc.x);
        acc.y = fmaf(p0.y, a01.y, acc.y);
        acc.z = fmaf(p0.y, a23.x, acc.z);
        acc.w = fmaf(p0.y, a23.y, acc.w);
        acc.x = fmaf(p1.y, b01.x, acc.x);
        acc.y = fmaf(p1.y, b01.y, acc.y);
        acc.z = fmaf(p1.y, b23.x, acc.z);
        acc.w = fmaf(p1.y, b23.y, acc.w);
    }
    if (i < end) {
        float2 p0 = g_pair[i];
        uint2 r0 = hs2[(size_t)__float_as_int(p0.x) * 16 + q];
        float2 a01 = __half22float2(u32_to_h2(r0.x));
        float2 a23 = __half22float2(u32_to_h2(r0.y));
        acc.x = fmaf(p0.y, a01.x, acc.x);
        acc.y = fmaf(p0.y, a01.y, acc.y);
        acc.z = fmaf(p0.y, a23.x, acc.z);
        acc.w = fmaf(p0.y, a23.y, acc.w);
    }

    float ds = g_dis[d];
    float4 bb = ((const float4*)b)[q];
    float4 r;
    r.x = fmaxf(fmaf(ds, acc.x, bb.x), 0.f);
    r.y = fmaxf(fmaf(ds, acc.y, bb.y), 0.f);
    r.z = fmaxf(fmaf(ds, acc.z, bb.z), 0.f);
    r.w = fmaxf(fmaf(ds, acc.w, bb.w), 0.f);
    return r;
}

// ---------------------------------------------------------------------------
// GEMM layer 1: g_hs = fp16( dis[row] * (X @ W1) ).  R10-exact.
__global__ __launch_bounds__(256) void gemm_hs_kernel(
    const float* __restrict__ X, const float* __restrict__ W, int n)
{
    __shared__ float sW[DD * DD];
    __shared__ float sX[DD * DD];

    int t = threadIdx.x;
    int row0 = blockIdx.x * 64;

    {
        float4* sW4 = (float4*)sW;
        const float4* W4 = (const float4*)W;
        #pragma unroll
        for (int i = 0; i < 4; i++) sW4[t + i * 256] = W4[t + i * 256];
    }
    {
        float4* sX4 = (float4*)sX;
        const float4* X4 = (const float4*)X;
        if (row0 + 64 <= n) {
            #pragma unroll
            for (int i = 0; i < 4; i++) sX4[t + i * 256] = X4[(size_t)row0 * 16 + t + i * 256];
        } else {
            #pragma unroll
            for (int i = 0; i < 4; i++) {
                int idx = t + i * 256;
                int r = idx >> 4;
                float4 v = make_float4(0.f, 0.f, 0.f, 0.f);
                if (row0 + r < n) v = X4[(size_t)row0 * 16 + idx];
                sX4[idx] = v;
            }
        }
    }
    __syncthreads();

    int rg = (t >> 4) * 4;
    int c0 = (t & 15) * 4;

    float a[4][4];
    #pragma unroll
    for (int i = 0; i < 4; i++)
        #pragma unroll
        for (int j = 0; j < 4; j++) a[i][j] = 0.f;

    #pragma unroll 16
    for (int k = 0; k < 64; k++) {
        float4 wv = *(const float4*)(sW + k * 64 + c0);
        #pragma unroll
        for (int i = 0; i < 4; i++) {
            float xv = sX[(rg + i) * 64 + k];
            a[i][0] = fmaf(xv, wv.x, a[i][0]);
            a[i][1] = fmaf(xv, wv.y, a[i][1]);
            a[i][2] = fmaf(xv, wv.z, a[i][2]);
            a[i][3] = fmaf(xv, wv.w, a[i][3]);
        }
    }

    uint2* hp = (uint2*)g_hs;
    #pragma unroll
    for (int i = 0; i < 4; i++) {
        int r = row0 + rg + i;
        if (r < n) {
            float ds = g_dis[r];
            __half2 h01 = __floats2half2_rn(a[i][0] * ds, a[i][1] * ds);
            __half2 h23 = __floats2half2_rn(a[i][2] * ds, a[i][3] * ds);
            hp[(size_t)r * 16 + (c0 >> 2)] = make_uint2(h2_to_u32(h01), h2_to_u32(h23));
        }
    }
}

// ---------------------------------------------------------------------------
// FUSED gather1 + GEMM2: block owns 64 nodes.  R14-exact.
// Phase A: gather x1 for those 64 nodes from g_hs (read-only), write to smem
//          X-tile AND g_x1.
// Phase B: g_hs2 = fp16( dis * (x1tile @ W2) )  — double-buffered, race-free.
__global__ __launch_bounds__(256) void fused_gather1_gemm2_kernel(
    const float* __restrict__ b1, const float* __restrict__ W, int n)
{
    __shared__ float sW[DD * DD];
    __shared__ float sX[DD * DD];

    int t = threadIdx.x;
    int row0 = blockIdx.x * 64;

    {   // W2 into smem
        float4* sW4 = (float4*)sW;
        const float4* W4 = (const float4*)W;
        #pragma unroll
        for (int i = 0; i < 4; i++) sW4[t + i * 256] = W4[t + i * 256];
    }

    // Phase A: gather.  sub = node-within-round (16 per round), q = column chunk.
    int sub = t >> 4;
    int q = t & 15;
    #pragma unroll
    for (int rnd = 0; rnd < 4; rnd++) {
        int local = rnd * 16 + sub;          // 0..63
        int d = row0 + local;
        float4 r = make_float4(0.f, 0.f, 0.f, 0.f);
        if (d < n) {
            r = gather_node(g_hs, d, q, b1);
            ((float4*)g_x1)[(size_t)d * 16 + q] = r;      // for final combine
        }
        *(float4*)(sX + local * 64 + q * 4) = r;          // X-tile for GEMM2
    }
    __syncthreads();

    // Phase B: GEMM (identical mainloop), writes g_hs2
    int rg = sub * 4;
    int c0 = q * 4;

    float a[4][4];
    #pragma unroll
    for (int i = 0; i < 4; i++)
        #pragma unroll
        for (int j = 0; j < 4; j++) a[i][j] = 0.f;

    #pragma unroll 16
    for (int k = 0; k < 64; k++) {
        float4 wv = *(const float4*)(sW + k * 64 + c0);
        #pragma unroll
        for (int i = 0; i < 4; i++) {
            float xv = sX[(rg + i) * 64 + k];
            a[i][0] = fmaf(xv, wv.x, a[i][0]);
            a[i][1] = fmaf(xv, wv.y, a[i][1]);
            a[i][2] = fmaf(xv, wv.z, a[i][2]);
            a[i][3] = fmaf(xv, wv.w, a[i][3]);
        }
    }

    uint2* hp = (uint2*)g_hs2;
    #pragma unroll
    for (int i = 0; i < 4; i++) {
        int r = row0 + rg + i;
        if (r < n) {
            float ds = g_dis[r];
            __half2 h01 = __floats2half2_rn(a[i][0] * ds, a[i][1] * ds);
            __half2 h23 = __floats2half2_rn(a[i][2] * ds, a[i][3] * ds);
            hp[(size_t)r * 16 + (c0 >> 2)] = make_uint2(h2_to_u32(h01), h2_to_u32(h23));
        }
    }
}

// ---------------------------------------------------------------------------
// Final gather (layer 2, reads g_hs2) + combine: out = 0.5*(x1 + relu(...)).
__global__ __launch_bounds__(256) void gather2_kernel(
    const float* __restrict__ b, float* __restrict__ out, int n)
{
    int gid = blockIdx.x * blockDim.x + threadIdx.x;
    int d = gid >> 4;
    if (d >= n) return;
    int q = gid & 15;

    float4 r = gather_node(g_hs2, d, q, b);
    size_t oi = (size_t)d * 16 + q;
    float4 x1v = ((const float4*)g_x1)[oi];
    r.x = 0.5f * (x1v.x + r.x);
    r.y = 0.5f * (x1v.y + r.y);
    r.z = 0.5f * (x1v.z + r.z);
    r.w = 0.5f * (x1v.w + r.w);
    ((float4*)out)[oi] = r;
}

// ---------------------------------------------------------------------------
extern "C" void kernel_launch(void* const* d_in, const int* in_sizes, int n_in,
                              void* d_out, int out_size) {
    const float* x  = (const float*)d_in[0];
    const int*   ei = (const int*)d_in[1];      // int32 (JAX default x64-disabled)
    const float* ew = (const float*)d_in[2];
    const float* W1 = (const float*)d_in[3];
    const float* b1 = (const float*)d_in[4];
    const float* W2 = (const float*)d_in[5];
    const float* b2 = (const float*)d_in[6];
    float* out = (float*)d_out;

    int n = in_sizes[0] / DD;      // 100000
    int E = in_sizes[2];           // 1200000

    int nb_n   = (n + 255) / 256;
    int nb_e   = (E + 255) / 256;
    int nb_gat = (int)(((long long)n * 16 + 255) / 256);
    int nb_g   = (n + 63) / 64;

    // CSR + degree (shared across both layers) — serial single-stream chain
    init_kernel<<<nb_n, 256>>>(n);
    count_kernel<<<nb_e, 256>>>(ei, ew, E);
    scan_dis_kernel<<<1, 1024>>>(n);               // scan + dis fused (the one delta)
    fill_kernel<<<nb_e, 256>>>(ei, ew, E);

    // Layer 1 GEMM
    gemm_hs_kernel<<<nb_g, 256>>>(x, W1, n);
    // gather1 + GEMM2 fused (race-free: reads g_hs, writes g_hs2)
    fused_gather1_gemm2_kernel<<<nb_g, 256>>>(b1, W2, n);
    // Layer 2 gather + combine (reads g_hs2)
    gather2_kernel<<<nb_gat, 256>>>(b2, out, n);
}

// round 17
// speedup vs baseline: 1.3723x; 1.3723x over previous
#include <cuda_runtime.h>
#include <cuda_fp16.h>
#include <cstring>

#define DD 64
#define NMAX 100000
#define EMAX 1200000

// Portable bit-casts
__device__ __forceinline__ unsigned h2_to_u32(__half2 h) { unsigned u; memcpy(&u, &h, 4); return u; }
__device__ __forceinline__ __half2 u32_to_h2(unsigned u) { __half2 h; memcpy(&h, &u, 4); return h; }

// Scratch (allocation-free rule: __device__ globals). 16B-aligned.
__device__ __align__(16) float  g_deg[NMAX];
__device__ __align__(16) float  g_dis[NMAX];
__device__ __align__(16) int    g_cnt[NMAX];
__device__ __align__(16) int    g_row[NMAX + 1];
__device__ __align__(16) int    g_cur[NMAX];
__device__ __align__(16) float2 g_pair[EMAX];       // (src*16 as int bits, weight), bucketed by dst
__device__ __align__(16) __half g_hs [NMAX * DD];   // fp16: dis*(X@W1)
__device__ __align__(16) __half g_hs2[NMAX * DD];   // fp16: dis*(x1@W2)
__device__ __align__(16) float  g_x1 [NMAX * DD];   // layer-1 output (fp32)

// ---------------------------------------------------------------------------
// init: cnt = 0, deg = 1 (self-loop weight)
__global__ void init_kernel(int n) {
    int i = blockIdx.x * blockDim.x + threadIdx.x;
    if (i < n) { g_cnt[i] = 0; g_deg[i] = 1.0f; }
}

// count in-degree + weighted degree.  edge_index is INT32: src = ei[e], dst = ei[E+e].
__global__ void count_kernel(const int* __restrict__ ei,
                             const float* __restrict__ ew, int E) {
    int e = blockIdx.x * blockDim.x + threadIdx.x;
    if (e < E) {
        int d = ei[E + e];
        atomicAdd(&g_cnt[d], 1);
        atomicAdd(&g_deg[d], ew[e]);
    }
}

// single-block exclusive scan of g_cnt -> g_row, g_cur; g_row[n] = E
// (dis deliberately NOT fused — R16 measured that fusion at +108 us)
__global__ __launch_bounds__(1024) void scan_kernel(int n) {
    __shared__ int ssum[1024];
    int t = threadIdx.x;
    int chunk = (n + 1023) >> 10;
    int beg = t * chunk;
    int end = min(n, beg + chunk);
    int s = 0;
    for (int i = beg; i < end; i++) s += g_cnt[i];
    ssum[t] = s;
    __syncthreads();
    if (t == 0) {
        int acc = 0;
        for (int i = 0; i < 1024; i++) { int v = ssum[i]; ssum[i] = acc; acc += v; }
        g_row[n] = acc;
    }
    __syncthreads();
    int acc = ssum[t];
    for (int i = beg; i < end; i++) {
        int c = g_cnt[i];
        g_row[i] = acc;
        g_cur[i] = acc;
        acc += c;
    }
}

// dis = rsqrt(deg)   (deg >= 1 always)
__global__ void dis_kernel(int n) {
    int i = blockIdx.x * blockDim.x + threadIdx.x;
    if (i < n) g_dis[i] = rsqrtf(g_deg[i]);
}

// bucket edges by dst: g_pair[slot] = (src*16, w)
// DELTA vs R14: store src<<4 (= row base in uint2 units) so the gather inner
// loop skips one IMAD per edge-lane.
__global__ void fill_kernel(const int* __restrict__ ei,
                            const float* __restrict__ ew, int E) {
    int e = blockIdx.x * blockDim.x + threadIdx.x;
    if (e < E) {
        int s = ei[e];
        int d = ei[E + e];
        int p = atomicAdd(&g_cur[d], 1);
        g_pair[p] = make_float2(__int_as_float(s << 4), ew[e]);
    }
}

// ---------------------------------------------------------------------------
// Per-thread gather core (R10/R14-proven loop; pair.x is the PRE-SCALED row
// base src*16).  16 lanes per node, lane q owns 4 fp16 columns (8B).
__device__ __forceinline__ float4 gather_node(const __half* __restrict__ hsrc,
                                              int d, int q, const float* __restrict__ b) {
    const uint2* __restrict__ hs2 = (const uint2*)hsrc;
    size_t oi = (size_t)d * 16 + q;

    uint2 self = hs2[oi];
    float2 s01 = __half22float2(u32_to_h2(self.x));
    float2 s23 = __half22float2(u32_to_h2(self.y));
    float4 acc = make_float4(s01.x, s01.y, s23.x, s23.y);

    int beg = g_row[d];
    int end = g_row[d + 1];

    int i = beg;
    for (; i + 2 <= end; i += 2) {
        float2 p0 = g_pair[i];
        float2 p1 = g_pair[i + 1];
        uint2 r0 = hs2[(unsigned)(__float_as_int(p0.x) + q)];
        uint2 r1 = hs2[(unsigned)(__float_as_int(p1.x) + q)];
        float2 a01 = __half22float2(u32_to_h2(r0.x));
        float2 a23 = __half22float2(u32_to_h2(r0.y));
        float2 b01 = __half22float2(u32_to_h2(r1.x));
        float2 b23 = __half22float2(u32_to_h2(r1.y));
        acc.x = fmaf(p0.y, a01.x, acc.x);
        acc.y = fmaf(p0.y, a01.y, acc.y);
        acc.z = fmaf(p0.y, a23.x, acc.z);
        acc.w = fmaf(p0.y, a23.y, acc.w);
        acc.x = fmaf(p1.y, b01.x, acc.x);
        acc.y = fmaf(p1.y, b01.y, acc.y);
        acc.z = fmaf(p1.y, b23.x, acc.z);
        acc.w = fmaf(p1.y, b23.y, acc.w);
    }
    if (i < end) {
        float2 p0 = g_pair[i];
        uint2 r0 = hs2[(unsigned)(__float_as_int(p0.x) + q)];
        float2 a01 = __half22float2(u32_to_h2(r0.x));
        float2 a23 = __half22float2(u32_to_h2(r0.y));
        acc.x = fmaf(p0.y, a01.x, acc.x);
        acc.y = fmaf(p0.y, a01.y, acc.y);
        acc.z = fmaf(p0.y, a23.x, acc.z);
        acc.w = fmaf(p0.y, a23.y, acc.w);
    }

    float ds = g_dis[d];
    float4 bb = ((const float4*)b)[q];
    float4 r;
    r.x = fmaxf(fmaf(ds, acc.x, bb.x), 0.f);
    r.y = fmaxf(fmaf(ds, acc.y, bb.y), 0.f);
    r.z = fmaxf(fmaf(ds, acc.z, bb.z), 0.f);
    r.w = fmaxf(fmaf(ds, acc.w, bb.w), 0.f);
    return r;
}

// ---------------------------------------------------------------------------
// GEMM layer 1: g_hs = fp16( dis[row] * (X @ W1) ).  R10-exact.
__global__ __launch_bounds__(256) void gemm_hs_kernel(
    const float* __restrict__ X, const float* __restrict__ W, int n)
{
    __shared__ float sW[DD * DD];
    __shared__ float sX[DD * DD];

    int t = threadIdx.x;
    int row0 = blockIdx.x * 64;

    {
        float4* sW4 = (float4*)sW;
        const float4* W4 = (const float4*)W;
        #pragma unroll
        for (int i = 0; i < 4; i++) sW4[t + i * 256] = W4[t + i * 256];
    }
    {
        float4* sX4 = (float4*)sX;
        const float4* X4 = (const float4*)X;
        if (row0 + 64 <= n) {
            #pragma unroll
            for (int i = 0; i < 4; i++) sX4[t + i * 256] = X4[(size_t)row0 * 16 + t + i * 256];
        } else {
            #pragma unroll
            for (int i = 0; i < 4; i++) {
                int idx = t + i * 256;
                int r = idx >> 4;
                float4 v = make_float4(0.f, 0.f, 0.f, 0.f);
                if (row0 + r < n) v = X4[(size_t)row0 * 16 + idx];
                sX4[idx] = v;
            }
        }
    }
    __syncthreads();

    int rg = (t >> 4) * 4;
    int c0 = (t & 15) * 4;

    float a[4][4];
    #pragma unroll
    for (int i = 0; i < 4; i++)
        #pragma unroll
        for (int j = 0; j < 4; j++) a[i][j] = 0.f;

    #pragma unroll 16
    for (int k = 0; k < 64; k++) {
        float4 wv = *(const float4*)(sW + k * 64 + c0);
        #pragma unroll
        for (int i = 0; i < 4; i++) {
            float xv = sX[(rg + i) * 64 + k];
            a[i][0] = fmaf(xv, wv.x, a[i][0]);
            a[i][1] = fmaf(xv, wv.y, a[i][1]);
            a[i][2] = fmaf(xv, wv.z, a[i][2]);
            a[i][3] = fmaf(xv, wv.w, a[i][3]);
        }
    }

    uint2* hp = (uint2*)g_hs;
    #pragma unroll
    for (int i = 0; i < 4; i++) {
        int r = row0 + rg + i;
        if (r < n) {
            float ds = g_dis[r];
            __half2 h01 = __floats2half2_rn(a[i][0] * ds, a[i][1] * ds);
            __half2 h23 = __floats2half2_rn(a[i][2] * ds, a[i][3] * ds);
            hp[(size_t)r * 16 + (c0 >> 2)] = make_uint2(h2_to_u32(h01), h2_to_u32(h23));
        }
    }
}

// ---------------------------------------------------------------------------
// FUSED gather1 + GEMM2: block owns 64 nodes.  R14-exact.
__global__ __launch_bounds__(256) void fused_gather1_gemm2_kernel(
    const float* __restrict__ b1, const float* __restrict__ W, int n)
{
    __shared__ float sW[DD * DD];
    __shared__ float sX[DD * DD];

    int t = threadIdx.x;
    int row0 = blockIdx.x * 64;

    {   // W2 into smem
        float4* sW4 = (float4*)sW;
        const float4* W4 = (const float4*)W;
        #pragma unroll
        for (int i = 0; i < 4; i++) sW4[t + i * 256] = W4[t + i * 256];
    }

    // Phase A: gather.  sub = node-within-round (16 per round), q = column chunk.
    int sub = t >> 4;
    int q = t & 15;
    #pragma unroll
    for (int rnd = 0; rnd < 4; rnd++) {
        int local = rnd * 16 + sub;          // 0..63
        int d = row0 + local;
        float4 r = make_float4(0.f, 0.f, 0.f, 0.f);
        if (d < n) {
            r = gather_node(g_hs, d, q, b1);
            ((float4*)g_x1)[(size_t)d * 16 + q] = r;      // for final combine
        }
        *(float4*)(sX + local * 64 + q * 4) = r;          // X-tile for GEMM2
    }
    __syncthreads();

    // Phase B: GEMM (identical mainloop), writes g_hs2
    int rg = sub * 4;
    int c0 = q * 4;

    float a[4][4];
    #pragma unroll
    for (int i = 0; i < 4; i++)
        #pragma unroll
        for (int j = 0; j < 4; j++) a[i][j] = 0.f;

    #pragma unroll 16
    for (int k = 0; k < 64; k++) {
        float4 wv = *(const float4*)(sW + k * 64 + c0);
        #pragma unroll
        for (int i = 0; i < 4; i++) {
            float xv = sX[(rg + i) * 64 + k];
            a[i][0] = fmaf(xv, wv.x, a[i][0]);
            a[i][1] = fmaf(xv, wv.y, a[i][1]);
            a[i][2] = fmaf(xv, wv.z, a[i][2]);
            a[i][3] = fmaf(xv, wv.w, a[i][3]);
        }
    }

    uint2* hp = (uint2*)g_hs2;
    #pragma unroll
    for (int i = 0; i < 4; i++) {
        int r = row0 + rg + i;
        if (r < n) {
            float ds = g_dis[r];
            __half2 h01 = __floats2half2_rn(a[i][0] * ds, a[i][1] * ds);
            __half2 h23 = __floats2half2_rn(a[i][2] * ds, a[i][3] * ds);
            hp[(size_t)r * 16 + (c0 >> 2)] = make_uint2(h2_to_u32(h01), h2_to_u32(h23));
        }
    }
}

// ---------------------------------------------------------------------------
// Final gather (layer 2, reads g_hs2) + combine: out = 0.5*(x1 + relu(...)).
__global__ __launch_bounds__(256) void gather2_kernel(
    const float* __restrict__ b, float* __restrict__ out, int n)
{
    int gid = blockIdx.x * blockDim.x + threadIdx.x;
    int d = gid >> 4;
    if (d >= n) return;
    int q = gid & 15;

    float4 r = gather_node(g_hs2, d, q, b);
    size_t oi = (size_t)d * 16 + q;
    float4 x1v = ((const float4*)g_x1)[oi];
    r.x = 0.5f * (x1v.x + r.x);
    r.y = 0.5f * (x1v.y + r.y);
    r.z = 0.5f * (x1v.z + r.z);
    r.w = 0.5f * (x1v.w + r.w);
    ((float4*)out)[oi] = r;
}

// ---------------------------------------------------------------------------
extern "C" void kernel_launch(void* const* d_in, const int* in_sizes, int n_in,
                              void* d_out, int out_size) {
    const float* x  = (const float*)d_in[0];
    const int*   ei = (const int*)d_in[1];      // int32 (JAX default x64-disabled)
    const float* ew = (const float*)d_in[2];
    const float* W1 = (const float*)d_in[3];
    const float* b1 = (const float*)d_in[4];
    const float* W2 = (const float*)d_in[5];
    const float* b2 = (const float*)d_in[6];
    float* out = (float*)d_out;

    int n = in_sizes[0] / DD;      // 100000
    int E = in_sizes[2];           // 1200000

    int nb_n   = (n + 255) / 256;
    int nb_e   = (E + 255) / 256;
    int nb_gat = (int)(((long long)n * 16 + 255) / 256);
    int nb_g   = (n + 63) / 64;

    // CSR + degree (shared across both layers) — R14-exact launch structure
    init_kernel<<<nb_n, 256>>>(n);
    count_kernel<<<nb_e, 256>>>(ei, ew, E);
    scan_kernel<<<1, 1024>>>(n);
    dis_kernel<<<nb_n, 256>>>(n);
    fill_kernel<<<nb_e, 256>>>(ei, ew, E);

    // Layer 1 GEMM
    gemm_hs_kernel<<<nb_g, 256>>>(x, W1, n);
    // gather1 + GEMM2 fused (race-free: reads g_hs, writes g_hs2)
    fused_gather1_gemm2_kernel<<<nb_g, 256>>>(b1, W2, n);
    // Layer 2 gather + combine (reads g_hs2)
    gather2_kernel<<<nb_gat, 256>>>(b2, out, n);
}